// round 15
// baseline (speedup 1.0000x reference)
#include <cuda_runtime.h>
#include <cuda_bf16.h>
#include <math.h>

#define NN    50000
#define DIMF  128
#define NH    8
#define EE    800000
#define NRELC 2000
#define TT    200000
#define RRULE 50000
#define BB    10000
#define TV_INV 0.029462782549439483f   // 1/(3*sqrt(128))
#define LOG2E 1.4426950408889634f

// gemm tiling: 8 groups of 128 threads, 8 nodes per group -> 64 nodes/block
#define GNPB   8
#define GGRP   8
#define GNODES (GNPB * GGRP)
#define GB     ((NN + GNODES - 1) / GNODES)       // 782 gemm blocks per graph
#define RB     ((2 * NRELC + 31) / 32)            // 125 normrel blocks
#define HB     ((2 * EE + 1023) / 1024)           // 1563 hist/scatter blocks
#define TRB    12500                              // transe blocks (256 thr)
#define RULEB  (((RRULE / 4) + 7) / 8)            // 1563 rule-rs blocks (256 thr)
#define GATB   ((BB * DIMF + 255) / 256)          // 5000 gather blocks (256 thr)
#define RFB    ((RRULE + 255) / 256)              // 196 rule-combine blocks
#define ZTB    ((2 * NN + 255) / 256)             // 391 tail-zero blocks (256 thr)
#define AGGB   1200                               // agg work-queue blocks

// ---------------- device scratch (zero-initialized at module load) -------------
__device__ __align__(16) float d_x[2 * NN * DIMF];
__device__ __align__(16) float d_h[2 * NN * DIMF];   // h (fp32), reused per layer
__device__ float               d_asrc[2 * NN * NH];  // prescaled by log2(e)
__device__ float               d_adst[2 * NN * NH];  // prescaled by log2(e)
__device__ __align__(16) float d_feat[2 * NN * DIMF];
__device__ __align__(16) __nv_bfloat16 d_gnorm[2 * NN * DIMF];
__device__ __align__(16) __nv_bfloat16 d_rnorm[2 * NRELC * DIMF];
__device__ float d_rs[2 * RRULE];                    // rule tv scores
__device__ int d_cnt[2 * NN];     // zero at load; re-zeroed at tail of each run
__device__ int d_off[2 * (NN + 1)];
__device__ int d_cur[2 * NN];
__device__ __align__(16) int d_csrc[2 * EE];
__device__ unsigned int d_wq[2];  // work-queue counters (agg0, agg1); tail-zeroed

// ---------------- packed helpers ----------------------------------------------
__device__ __forceinline__ unsigned long long pack2(float x, float y) {
    unsigned long long r;
    asm("mov.b64 %0, {%1, %2};" : "=l"(r) : "f"(x), "f"(y));
    return r;
}
__device__ __forceinline__ void unpack2(unsigned long long v, float& x, float& y) {
    asm("mov.b64 {%0, %1}, %2;" : "=f"(x), "=f"(y) : "l"(v));
}
__device__ __forceinline__ unsigned long long fma2(unsigned long long a,
                                                   unsigned long long b,
                                                   unsigned long long c) {
    unsigned long long r;
    asm("fma.rn.f32x2 %0, %1, %2, %3;" : "=l"(r) : "l"(a), "l"(b), "l"(c));
    return r;
}
__device__ __forceinline__ float ex2(float x) {
    float r;
    asm("ex2.approx.f32 %0, %1;" : "=f"(r) : "f"(x));
    return r;
}
__device__ __forceinline__ uint2 pack_bf16x4(float a, float b, float c, float d) {
    __nv_bfloat162 p0 = __floats2bfloat162_rn(a, b);
    __nv_bfloat162 p1 = __floats2bfloat162_rn(c, d);
    uint2 u;
    u.x = *reinterpret_cast<unsigned int*>(&p0);
    u.y = *reinterpret_cast<unsigned int*>(&p1);
    return u;
}

// ================== device building blocks =====================================

__device__ __forceinline__ void dev_normrel(int b, const float* __restrict__ rel0,
                                            const float* __restrict__ rel1) {
    int wid = threadIdx.x >> 5, lane = threadIdx.x & 31;
    int row = b * 32 + wid;
    if (row >= 2 * NRELC) return;
    int g = row >= NRELC;
    int r = row - g * NRELC;
    const float* rel = g ? rel1 : rel0;
    float4 v = reinterpret_cast<const float4*>(rel + (size_t)r * DIMF)[lane];
    float s = v.x * v.x + v.y * v.y + v.z * v.z + v.w * v.w;
#pragma unroll
    for (int o = 16; o > 0; o >>= 1) s += __shfl_xor_sync(0xffffffffu, s, o);
    float sc = 1.0f / fmaxf(sqrtf(s), 1e-12f);
    uint2 bv = pack_bf16x4(v.x * sc, v.y * sc, v.z * sc, v.w * sc);
    reinterpret_cast<uint2*>(d_rnorm + (size_t)g * NRELC * DIMF +
                             (size_t)r * DIMF)[lane] = bv;
}

__device__ __forceinline__ void dev_hist(int b, const int* __restrict__ e0,
                                         const int* __restrict__ e1) {
    int idx = b * 1024 + threadIdx.x;
    if (idx >= 2 * EE) return;
    int g = idx >= EE;
    int e = idx - g * EE;
    const int* edg = g ? e1 : e0;
    atomicAdd(&d_cnt[g * NN + edg[EE + e]], 1);
}

__device__ __forceinline__ void dev_scatter(int b, const int* __restrict__ e0,
                                            const int* __restrict__ e1) {
    int idx = b * 1024 + threadIdx.x;
    if (idx >= 2 * EE) return;
    int g = idx >= EE;
    int e = idx - g * EE;
    const int* edg = g ? e1 : e0;
    int s = edg[e];
    int d = edg[EE + e];
    int p = atomicAdd(&d_cur[g * NN + d], 1);
    d_csrc[(size_t)g * EE + p] = s;
}

__device__ __forceinline__ void dev_scan(int* wsum, int g) {
    int t = threadIdx.x;
    int lane = t & 31, wid = t >> 5;
    const int NCH = (NN + 1023) / 1024;
    int run = 0;
    int val = (t < NN) ? d_cnt[g * NN + t] : 0;
    for (int c = 0; c < NCH; c++) {
        int inext = (c + 1) * 1024 + t;
        int vnext = (c + 1 < NCH && inext < NN) ? d_cnt[g * NN + inext] : 0;
        int incl = val;
#pragma unroll
        for (int o = 1; o < 32; o <<= 1) {
            int u = __shfl_up_sync(0xffffffffu, incl, o);
            if (lane >= o) incl += u;
        }
        if (lane == 31) wsum[wid] = incl;
        __syncthreads();
        if (wid == 0) {
            int ws = wsum[lane];
#pragma unroll
            for (int o = 1; o < 32; o <<= 1) {
                int u = __shfl_up_sync(0xffffffffu, ws, o);
                if (lane >= o) ws += u;
            }
            wsum[lane] = ws;
        }
        __syncthreads();
        int wb = (wid > 0) ? wsum[wid - 1] : 0;
        int i = c * 1024 + t;
        int excl = run + wb + incl - val;
        if (i < NN) {
            d_off[g * (NN + 1) + i] = excl;
            d_cur[g * NN + i] = excl;
        }
        run += wsum[31];
        __syncthreads();
        val = vnext;
    }
    if (t == 0) d_off[g * (NN + 1) + NN] = EE;
}

// gemm block with FUSED alpha epilogue; fp32 h out; alphas prescaled by log2(e)
__device__ __forceinline__ void dev_gemm_block(float* smem, int nodeblk, int g,
                                               const float* __restrict__ xsrc,
                                               const float* __restrict__ W,
                                               const float* __restrict__ a_s,
                                               const float* __restrict__ a_d) {
    int t = threadIdx.x;
    int grp = t >> 7, lt = t & 127;
    float* xst = smem + grp * (DIMF * GNPB);   // [d][u]: d*8+u
    int nb = nodeblk * GNODES + grp * GNPB;

    for (int k = lt; k < GNPB * DIMF; k += 128) {
        int u = k >> 7, d = k & 127;
        int n = nb + u;
        xst[d * GNPB + u] = (n < NN) ? xsrc[(size_t)n * DIMF + d] : 0.0f;
    }
    __syncthreads();

    unsigned long long a0 = 0, a1 = 0, a2 = 0, a3 = 0;
#pragma unroll 4
    for (int d = 0; d < DIMF; d++) {
        float w = __ldg(W + d * DIMF + lt);
        unsigned long long w2 = pack2(w, w);
        const ulonglong2* xr = reinterpret_cast<const ulonglong2*>(xst + d * GNPB);
        ulonglong2 p0 = xr[0];
        ulonglong2 p1 = xr[1];
        a0 = fma2(p0.x, w2, a0);
        a1 = fma2(p0.y, w2, a1);
        a2 = fma2(p1.x, w2, a2);
        a3 = fma2(p1.y, w2, a3);
    }
    float v[GNPB];
    unpack2(a0, v[0], v[1]);
    unpack2(a1, v[2], v[3]);
    unpack2(a2, v[4], v[5]);
    unpack2(a3, v[6], v[7]);

    float* hb = d_h + (size_t)g * NN * DIMF;
#pragma unroll
    for (int u = 0; u < GNPB; u++) {
        int n = nb + u;
        if (n < NN) hb[(size_t)n * DIMF + lt] = v[u];
    }

    // fused alpha (prescaled by log2e so agg can use raw ex2)
    float as = __ldg(a_s + lt) * LOG2E;
    float ad = __ldg(a_d + lt) * LOG2E;
    float* asrc = d_asrc + (size_t)g * NN * NH;
    float* adst = d_adst + (size_t)g * NN * NH;
    int head = lt >> 4;
#pragma unroll
    for (int u = 0; u < GNPB; u++) {
        float vs = v[u] * as;
        float vd = v[u] * ad;
#pragma unroll
        for (int o = 8; o > 0; o >>= 1) {
            vs += __shfl_down_sync(0xffffffffu, vs, o, 16);
            vd += __shfl_down_sync(0xffffffffu, vd, o, 16);
        }
        if ((lt & 15) == 0) {
            int n = nb + u;
            if (n < NN) {
                asrc[(size_t)n * NH + head] = vs;
                adst[(size_t)n * NH + head] = vd;
            }
        }
    }
}

// ================== combined launch kernels ===================================

// launch 0: gemm+alpha(g0, l0) || hist
__global__ void __launch_bounds__(1024) k_phaseB(const float* __restrict__ ent0,
                                                 const float* __restrict__ W0,
                                                 const float* __restrict__ a_s,
                                                 const float* __restrict__ a_d,
                                                 const int* __restrict__ e0,
                                                 const int* __restrict__ e1) {
    __shared__ __align__(16) float smem[GGRP * DIMF * GNPB];
    int b = blockIdx.x;
    if (b < GB) dev_gemm_block(smem, b, 0, ent0, W0, a_s, a_d);
    else        dev_hist(b - GB, e0, e1);
}

// launch 1: scan || gemm+alpha(g1, l0)
__global__ void __launch_bounds__(1024) k_phaseC(const float* __restrict__ ent1,
                                                 const float* __restrict__ W0,
                                                 const float* __restrict__ a_s,
                                                 const float* __restrict__ a_d) {
    __shared__ __align__(16) float smem[GGRP * DIMF * GNPB];
    int b = blockIdx.x;
    if (b < 2) dev_scan(reinterpret_cast<int*>(smem), b);
    else       dev_gemm_block(smem, b - 2, 1, ent1, W0, a_s, a_d);
}

// launch 2: scatter || normrel
__global__ void __launch_bounds__(1024) k_scatnorm(const int* __restrict__ e0,
                                                   const int* __restrict__ e1,
                                                   const float* __restrict__ rel0,
                                                   const float* __restrict__ rel1) {
    int b = blockIdx.x;
    if (b < HB) dev_scatter(b, e0, e1);
    else        dev_normrel(b - HB, rel0, rel1);
}

// gemm+alpha(layer1) both graphs, reading d_x
__global__ void __launch_bounds__(1024) k_gemm_l1(const float* __restrict__ W1,
                                                  const float* __restrict__ a_s,
                                                  const float* __restrict__ a_d) {
    __shared__ __align__(16) float smem[GGRP * DIMF * GNPB];
    int b = blockIdx.x;
    int g = b >= GB;
    dev_gemm_block(smem, b - g * GB, g, d_x + (size_t)g * NN * DIMF, W1,
                   a_s, a_d);
}

// ---- agg: R13 body (4-edge unroll, per-lane redundant weights) ----------------
// LAST=0: ELU -> d_x.  LAST=1: feat + bf16 gnorm.
template <int LAST>
__device__ __forceinline__ void agg_node(int g, int n, int lane) {
    const int* off = d_off + g * (NN + 1);
    const int* csrc = d_csrc + (size_t)g * EE;
    const float* hlane = d_h + (size_t)g * NN * DIMF + (lane << 2);
    const float* asb = d_asrc + (size_t)g * NN * NH;
    int head = lane >> 2;
    float adst_l = d_adst[(size_t)g * NN * NH + n * NH + head];

    int beg = off[n], end = off[n + 1];
    float4 acc = make_float4(0.f, 0.f, 0.f, 0.f);
    float den = 0.0f;

    int j = beg;
    for (; j + 4 <= end; j += 4) {
        int s0 = __ldg(csrc + j);
        int s1 = __ldg(csrc + j + 1);
        int s2 = __ldg(csrc + j + 2);
        int s3 = __ldg(csrc + j + 3);
        float al0 = __ldg(asb + s0 * NH + head);
        float al1 = __ldg(asb + s1 * NH + head);
        float al2 = __ldg(asb + s2 * NH + head);
        float al3 = __ldg(asb + s3 * NH + head);
        float4 h0 = *reinterpret_cast<const float4*>(hlane + (size_t)s0 * DIMF);
        float4 h1 = *reinterpret_cast<const float4*>(hlane + (size_t)s1 * DIMF);
        float4 h2 = *reinterpret_cast<const float4*>(hlane + (size_t)s2 * DIMF);
        float4 h3 = *reinterpret_cast<const float4*>(hlane + (size_t)s3 * DIMF);
        float v0 = al0 + adst_l; v0 = fmaxf(v0, 0.2f * v0);
        float v1 = al1 + adst_l; v1 = fmaxf(v1, 0.2f * v1);
        float v2 = al2 + adst_l; v2 = fmaxf(v2, 0.2f * v2);
        float v3 = al3 + adst_l; v3 = fmaxf(v3, 0.2f * v3);
        float w0 = ex2(v0);
        float w1 = ex2(v1);
        float w2 = ex2(v2);
        float w3 = ex2(v3);
        den += (w0 + w1) + (w2 + w3);
        acc.x = fmaf(w0, h0.x, acc.x);
        acc.y = fmaf(w0, h0.y, acc.y);
        acc.z = fmaf(w0, h0.z, acc.z);
        acc.w = fmaf(w0, h0.w, acc.w);
        acc.x = fmaf(w1, h1.x, acc.x);
        acc.y = fmaf(w1, h1.y, acc.y);
        acc.z = fmaf(w1, h1.z, acc.z);
        acc.w = fmaf(w1, h1.w, acc.w);
        acc.x = fmaf(w2, h2.x, acc.x);
        acc.y = fmaf(w2, h2.y, acc.y);
        acc.z = fmaf(w2, h2.z, acc.z);
        acc.w = fmaf(w2, h2.w, acc.w);
        acc.x = fmaf(w3, h3.x, acc.x);
        acc.y = fmaf(w3, h3.y, acc.y);
        acc.z = fmaf(w3, h3.z, acc.z);
        acc.w = fmaf(w3, h3.w, acc.w);
    }
    for (; j < end; j++) {
        int s0 = __ldg(csrc + j);
        float al0 = __ldg(asb + s0 * NH + head);
        float4 h0 = *reinterpret_cast<const float4*>(hlane + (size_t)s0 * DIMF);
        float v0 = al0 + adst_l; v0 = fmaxf(v0, 0.2f * v0);
        float w0 = ex2(v0);
        den += w0;
        acc.x = fmaf(w0, h0.x, acc.x);
        acc.y = fmaf(w0, h0.y, acc.y);
        acc.z = fmaf(w0, h0.z, acc.z);
        acc.w = fmaf(w0, h0.w, acc.w);
    }

    float inv = 1.0f / fmaxf(den, 1e-16f);
    acc.x *= inv; acc.y *= inv; acc.z *= inv; acc.w *= inv;

    if (LAST) {
        reinterpret_cast<float4*>(d_feat + (size_t)g * NN * DIMF +
                                  (size_t)n * DIMF)[lane] = acc;
        float s2 = acc.x * acc.x + acc.y * acc.y + acc.z * acc.z + acc.w * acc.w;
#pragma unroll
        for (int o = 16; o > 0; o >>= 1) s2 += __shfl_xor_sync(0xffffffffu, s2, o);
        float sc = 1.0f / fmaxf(sqrtf(s2), 1e-12f);
        uint2 bv = pack_bf16x4(acc.x * sc, acc.y * sc, acc.z * sc, acc.w * sc);
        reinterpret_cast<uint2*>(d_gnorm + (size_t)g * NN * DIMF +
                                 (size_t)n * DIMF)[lane] = bv;
    } else {
        acc.x = (acc.x > 0.f) ? acc.x : (__expf(acc.x) - 1.0f);
        acc.y = (acc.y > 0.f) ? acc.y : (__expf(acc.y) - 1.0f);
        acc.z = (acc.z > 0.f) ? acc.z : (__expf(acc.z) - 1.0f);
        acc.w = (acc.w > 0.f) ? acc.w : (__expf(acc.w) - 1.0f);
        reinterpret_cast<float4*>(d_x + (size_t)g * NN * DIMF +
                                  (size_t)n * DIMF)[lane] = acc;
    }
}

// work-queue driver: each warp pulls node indices from a global counter,
// prefetching the next index so the ATOMG latency hides behind node work.
// Perfect load balance across warps regardless of degree distribution.
template <int LAST>
__device__ __forceinline__ void agg_queue() {
    int lane = threadIdx.x & 31;
    unsigned int nf = 0;
    if (lane == 0) nf = atomicAdd(&d_wq[LAST], 1u);
    nf = __shfl_sync(0xffffffffu, nf, 0);
    while (nf < 2u * NN) {
        unsigned int nx = 0;
        if (lane == 0) nx = atomicAdd(&d_wq[LAST], 1u);
        nx = __shfl_sync(0xffffffffu, nx, 0);
        int g = nf >= (unsigned)NN;
        agg_node<LAST>(g, (int)nf - g * NN, lane);
        nf = nx;
    }
}

__global__ void __launch_bounds__(256, 5) k_agg0() { agg_queue<0>(); }
__global__ void __launch_bounds__(256, 5) k_agg1() { agg_queue<1>(); }

// ---- transE / rule-rs / gather merged ------------------------------------------
__device__ __forceinline__ float ad2(unsigned int a, unsigned int b, unsigned int c) {
    float2 fa = __bfloat1622float2(*reinterpret_cast<__nv_bfloat162*>(&a));
    float2 fb = __bfloat1622float2(*reinterpret_cast<__nv_bfloat162*>(&b));
    float2 fc = __bfloat1622float2(*reinterpret_cast<__nv_bfloat162*>(&c));
    return fabsf(fa.x + fb.x - fc.x) + fabsf(fa.y + fb.y - fc.y);
}
__device__ __forceinline__ float ad8(uint4 a, uint4 b, uint4 c) {
    return ad2(a.x, b.x, c.x) + ad2(a.y, b.y, c.y) +
           ad2(a.z, b.z, c.z) + ad2(a.w, b.w, c.w);
}
__device__ __forceinline__ float tv8(const __nv_bfloat16* gn,
                                     const __nv_bfloat16* rn,
                                     int hh, int tt, int rr, int lq) {
    const uint4* pa = reinterpret_cast<const uint4*>(gn + (size_t)hh * DIMF);
    const uint4* pb = reinterpret_cast<const uint4*>(rn + (size_t)rr * DIMF);
    const uint4* pc = reinterpret_cast<const uint4*>(gn + (size_t)tt * DIMF);
    uint4 a0 = pa[2 * lq], a1 = pa[2 * lq + 1];
    uint4 b0 = pb[2 * lq], b1 = pb[2 * lq + 1];
    uint4 c0 = pc[2 * lq], c1 = pc[2 * lq + 1];
    float s = ad8(a0, b0, c0) + ad8(a1, b1, c1);
    s += __shfl_xor_sync(0xffffffffu, s, 1);
    s += __shfl_xor_sync(0xffffffffu, s, 2);
    s += __shfl_xor_sync(0xffffffffu, s, 4);
    return 1.0f - s * TV_INV;
}

// launch 6: transe || rule-rs || gather  (all depend only on agg1 + normrel)
__global__ void __launch_bounds__(256) k_heads(
        const int* __restrict__ h0, const int* __restrict__ h1,
        const int* __restrict__ t0, const int* __restrict__ t1,
        const int* __restrict__ r0, const int* __restrict__ r1,
        const int* __restrict__ rh0, const int* __restrict__ rh1,
        const int* __restrict__ rt0, const int* __restrict__ rt1,
        const int* __restrict__ rr0, const int* __restrict__ rr1,
        float* __restrict__ outTv,
        const int* __restrict__ i0, const int* __restrict__ i1,
        float* __restrict__ outFeat) {
    int b = blockIdx.x;
    int g = blockIdx.y;
    const __nv_bfloat16* gn = d_gnorm + (size_t)g * NN * DIMF;
    const __nv_bfloat16* rn = d_rnorm + (size_t)g * NRELC * DIMF;
    if (b < TRB) {
        int gt = b * 256 + threadIdx.x;
        int warp = gt >> 5, lane = gt & 31;
        int sub = lane >> 3, lq = lane & 7;
        int w4 = warp * 4 + sub;
        if (w4 >= 2 * TT) return;
        const int* hI = g ? h1 : h0;
        const int* tI = g ? t1 : t0;
        const int* rI = g ? r1 : r0;
        float tv = tv8(gn, rn, hI[w4], tI[w4], rI[w4], lq);
        if (lq == 0) outTv[(size_t)g * 2 * TT + w4] = tv;
    } else if (b < TRB + RULEB) {
        int gt = (b - TRB) * 256 + threadIdx.x;
        int warp = gt >> 5, lane = gt & 31;
        if (warp * 4 >= RRULE) return;
        int sub = lane >> 3, lq = lane & 7;
        int w4 = warp * 4 + sub;
        const int* rh = g ? rh1 : rh0;
        const int* rt = g ? rt1 : rt0;
        const int* rr = g ? rr1 : rr0;
        float rs = tv8(gn, rn, rh[w4], rt[w4], rr[w4], lq);
        if (lq == 0) d_rs[(size_t)g * RRULE + w4] = rs;
    } else {
        int i = (b - TRB - RULEB) * 256 + threadIdx.x;
        if (i >= BB * DIMF) return;
        const int* idx = g ? i1 : i0;
        int bb = i >> 7, c = i & 127;
        outFeat[(size_t)g * BB * DIMF + i] =
            d_feat[(size_t)g * NN * DIMF + (size_t)idx[bb] * DIMF + c];
    }
}

// launch 7: rule combine (tiny) || tail-zero of d_cnt + work-queue counters
__global__ void __launch_bounds__(256) k_rulefin(
        const int* __restrict__ pm0, const int* __restrict__ pm1,
        const float* __restrict__ tvbase, float* __restrict__ outRule) {
    int b = blockIdx.x;
    int g = blockIdx.y;
    if (b < RFB) {
        int i = b * 256 + threadIdx.x;
        if (i >= RRULE) return;
        const int* prem = g ? pm1 : pm0;
        const float* tv = tvbase + (size_t)g * 2 * TT;
        float rs = d_rs[(size_t)g * RRULE + i];
        int p0 = prem[i * 2 + 0];
        int p1 = prem[i * 2 + 1];
        float f1 = (p0 < TT) ? tv[p0 * 2 + g] : 1.0f;
        float f2 = (p1 < TT) ? tv[p1 * 2 + g] : 1.0f;
        outRule[(size_t)g * RRULE + i] = 1.0f + f1 * f2 * (rs - 1.0f);
    } else {
        int i = (b - RFB) * 256 + threadIdx.x;
        if (i < 2 * NN) d_cnt[i] = 0;
        if (b == RFB && threadIdx.x < 2) d_wq[threadIdx.x] = 0u;   // idempotent
    }
}

// ---------------- host orchestration ------------------------------------------
static inline int nblk(long n, int t) { return (int)((n + t - 1) / t); }

extern "C" void kernel_launch(void* const* d_in, const int* in_sizes, int n_in,
                              void* d_out, int out_size) {
    const float* ent0 = (const float*)d_in[0];
    const float* ent1 = (const float*)d_in[1];
    const float* rel0 = (const float*)d_in[2];
    const float* rel1 = (const float*)d_in[3];
    const float* W    = (const float*)d_in[4];
    const float* a_s  = (const float*)d_in[5];
    const float* a_d  = (const float*)d_in[6];
    const int* dat0 = (const int*)d_in[7];
    const int* dat1 = (const int*)d_in[8];
    const int* edg0 = (const int*)d_in[9];
    const int* edg1 = (const int*)d_in[10];
    const int* h0 = (const int*)d_in[11];
    const int* t0 = (const int*)d_in[12];
    const int* r0 = (const int*)d_in[13];
    const int* h1 = (const int*)d_in[14];
    const int* t1 = (const int*)d_in[15];
    const int* r1 = (const int*)d_in[16];
    const int* rh0 = (const int*)d_in[17];
    const int* rt0 = (const int*)d_in[18];
    const int* rr0 = (const int*)d_in[19];
    const int* pm0 = (const int*)d_in[20];
    const int* rh1 = (const int*)d_in[21];
    const int* rt1 = (const int*)d_in[22];
    const int* rr1 = (const int*)d_in[23];
    const int* pm1 = (const int*)d_in[24];

    float* out      = (float*)d_out;
    float* out_feat = out;
    float* out_tv   = out + 2 * (size_t)BB * DIMF;
    float* out_rule = out_tv + 4 * (size_t)TT;

    const float* W0 = W;
    const float* W1 = W + (size_t)DIMF * DIMF;

    // 0: gemm+alpha(g0, l0) || hist
    k_phaseB<<<GB + HB, 1024>>>(ent0, W0, a_s, a_d, edg0, edg1);
    // 1: scan || gemm+alpha(g1, l0)
    k_phaseC<<<2 + GB, 1024>>>(ent1, W0, a_s, a_d);
    // 2: scatter || normrel
    k_scatnorm<<<HB + RB, 1024>>>(edg0, edg1, rel0, rel1);
    // 3: layer-0 aggregate (work-queue)  <-- the launch ncu profiles
    k_agg0<<<AGGB, 256>>>();
    // 4: layer-1 gemm+alpha
    k_gemm_l1<<<2 * GB, 1024>>>(W1, a_s + DIMF, a_d + DIMF);
    // 5: layer-1 aggregate (feat + bf16 gnorm; work-queue)
    k_agg1<<<AGGB, 256>>>();
    // 6: transe || rule-rs || gather
    k_heads<<<dim3(TRB + RULEB + GATB, 2), 256>>>(h0, h1, t0, t1, r0, r1,
                                                  rh0, rh1, rt0, rt1, rr0, rr1,
                                                  out_tv, dat0, dat1, out_feat);
    // 7: rule combine || tail-zero (d_cnt + d_wq)
    k_rulefin<<<dim3(RFB + ZTB, 2), 256>>>(pm0, pm1, out_tv, out_rule);

    (void)in_sizes; (void)n_in; (void)out_size;
}

// round 16
// speedup vs baseline: 1.0451x; 1.0451x over previous
#include <cuda_runtime.h>
#include <cuda_bf16.h>
#include <math.h>

#define NN    50000
#define DIMF  128
#define NH    8
#define EE    800000
#define NRELC 2000
#define TT    200000
#define RRULE 50000
#define BB    10000
#define TV_INV 0.029462782549439483f   // 1/(3*sqrt(128))
#define LOG2E 1.4426950408889634f

#define GNPB   8
#define GGRP   8
#define GNODES (GNPB * GGRP)
#define GB     ((NN + GNODES - 1) / GNODES)       // 782 gemm blocks per graph
#define RB     ((2 * NRELC + 31) / 32)            // 125 normrel blocks
#define HB     ((2 * EE + 1023) / 1024)           // 1563 hist/scatter blocks
#define TRB    12500                              // transe blocks (256 thr)
#define RULEB  (((RRULE / 4) + 7) / 8)            // 1563 rule-rs blocks
#define GATB   ((BB * DIMF + 255) / 256)          // 5000 gather blocks
#define RFB    ((RRULE + 255) / 256)              // 196 rule-combine blocks
#define ZTB    ((2 * NN + 255) / 256)             // 391 tail-zero blocks

// ---------------- device scratch (zero-initialized at module load) -------------
__device__ __align__(16) float d_x[2 * NN * DIMF];
__device__ __align__(16) float d_h[2 * NN * DIMF];
__device__ float               d_asrc[2 * NN * NH];  // prescaled by log2(e)
__device__ float               d_adst[2 * NN * NH];  // prescaled by log2(e)
__device__ __align__(16) float d_feat[2 * NN * DIMF];
__device__ __align__(16) __nv_bfloat16 d_gnorm[2 * NN * DIMF];
__device__ __align__(16) __nv_bfloat16 d_rnorm[2 * NRELC * DIMF];
__device__ float d_rs[2 * RRULE];
__device__ int d_cnt[2 * NN];
__device__ int d_off[2 * (NN + 1)];
__device__ int d_cur[2 * NN];
__device__ __align__(16) int d_csrc[2 * EE];

// ---------------- packed helpers ----------------------------------------------
__device__ __forceinline__ unsigned long long pack2(float x, float y) {
    unsigned long long r;
    asm("mov.b64 %0, {%1, %2};" : "=l"(r) : "f"(x), "f"(y));
    return r;
}
__device__ __forceinline__ void unpack2(unsigned long long v, float& x, float& y) {
    asm("mov.b64 {%0, %1}, %2;" : "=f"(x), "=f"(y) : "l"(v));
}
__device__ __forceinline__ unsigned long long fma2(unsigned long long a,
                                                   unsigned long long b,
                                                   unsigned long long c) {
    unsigned long long r;
    asm("fma.rn.f32x2 %0, %1, %2, %3;" : "=l"(r) : "l"(a), "l"(b), "l"(c));
    return r;
}
__device__ __forceinline__ float ex2(float x) {
    float r;
    asm("ex2.approx.f32 %0, %1;" : "=f"(r) : "f"(x));
    return r;
}
__device__ __forceinline__ uint2 pack_bf16x4(float a, float b, float c, float d) {
    __nv_bfloat162 p0 = __floats2bfloat162_rn(a, b);
    __nv_bfloat162 p1 = __floats2bfloat162_rn(c, d);
    uint2 u;
    u.x = *reinterpret_cast<unsigned int*>(&p0);
    u.y = *reinterpret_cast<unsigned int*>(&p1);
    return u;
}

// ================== device building blocks =====================================

__device__ __forceinline__ void dev_normrel(int b, const float* __restrict__ rel0,
                                            const float* __restrict__ rel1) {
    int wid = threadIdx.x >> 5, lane = threadIdx.x & 31;
    int row = b * 32 + wid;
    if (row >= 2 * NRELC) return;
    int g = row >= NRELC;
    int r = row - g * NRELC;
    const float* rel = g ? rel1 : rel0;
    float4 v = reinterpret_cast<const float4*>(rel + (size_t)r * DIMF)[lane];
    float s = v.x * v.x + v.y * v.y + v.z * v.z + v.w * v.w;
#pragma unroll
    for (int o = 16; o > 0; o >>= 1) s += __shfl_xor_sync(0xffffffffu, s, o);
    float sc = 1.0f / fmaxf(sqrtf(s), 1e-12f);
    uint2 bv = pack_bf16x4(v.x * sc, v.y * sc, v.z * sc, v.w * sc);
    reinterpret_cast<uint2*>(d_rnorm + (size_t)g * NRELC * DIMF +
                             (size_t)r * DIMF)[lane] = bv;
}

__device__ __forceinline__ void dev_hist(int b, const int* __restrict__ e0,
                                         const int* __restrict__ e1) {
    int idx = b * 1024 + threadIdx.x;
    if (idx >= 2 * EE) return;
    int g = idx >= EE;
    int e = idx - g * EE;
    const int* edg = g ? e1 : e0;
    atomicAdd(&d_cnt[g * NN + edg[EE + e]], 1);
}

__device__ __forceinline__ void dev_scatter(int b, const int* __restrict__ e0,
                                            const int* __restrict__ e1) {
    int idx = b * 1024 + threadIdx.x;
    if (idx >= 2 * EE) return;
    int g = idx >= EE;
    int e = idx - g * EE;
    const int* edg = g ? e1 : e0;
    int s = edg[e];
    int d = edg[EE + e];
    int p = atomicAdd(&d_cur[g * NN + d], 1);
    d_csrc[(size_t)g * EE + p] = s;
}

__device__ __forceinline__ void dev_scan(int* wsum, int g) {
    int t = threadIdx.x;
    int lane = t & 31, wid = t >> 5;
    const int NCH = (NN + 1023) / 1024;
    int run = 0;
    int val = (t < NN) ? d_cnt[g * NN + t] : 0;
    for (int c = 0; c < NCH; c++) {
        int inext = (c + 1) * 1024 + t;
        int vnext = (c + 1 < NCH && inext < NN) ? d_cnt[g * NN + inext] : 0;
        int incl = val;
#pragma unroll
        for (int o = 1; o < 32; o <<= 1) {
            int u = __shfl_up_sync(0xffffffffu, incl, o);
            if (lane >= o) incl += u;
        }
        if (lane == 31) wsum[wid] = incl;
        __syncthreads();
        if (wid == 0) {
            int ws = wsum[lane];
#pragma unroll
            for (int o = 1; o < 32; o <<= 1) {
                int u = __shfl_up_sync(0xffffffffu, ws, o);
                if (lane >= o) ws += u;
            }
            wsum[lane] = ws;
        }
        __syncthreads();
        int wb = (wid > 0) ? wsum[wid - 1] : 0;
        int i = c * 1024 + t;
        int excl = run + wb + incl - val;
        if (i < NN) {
            d_off[g * (NN + 1) + i] = excl;
            d_cur[g * NN + i] = excl;
        }
        run += wsum[31];
        __syncthreads();
        val = vnext;
    }
    if (t == 0) d_off[g * (NN + 1) + NN] = EE;
}

// gemm block with FUSED alpha epilogue; fp32 h out; alphas prescaled by log2(e)
__device__ __forceinline__ void dev_gemm_block(float* smem, int nodeblk, int g,
                                               const float* __restrict__ xsrc,
                                               const float* __restrict__ W,
                                               const float* __restrict__ a_s,
                                               const float* __restrict__ a_d) {
    int t = threadIdx.x;
    int grp = t >> 7, lt = t & 127;
    float* xst = smem + grp * (DIMF * GNPB);
    int nb = nodeblk * GNODES + grp * GNPB;

    for (int k = lt; k < GNPB * DIMF; k += 128) {
        int u = k >> 7, d = k & 127;
        int n = nb + u;
        xst[d * GNPB + u] = (n < NN) ? xsrc[(size_t)n * DIMF + d] : 0.0f;
    }
    __syncthreads();

    unsigned long long a0 = 0, a1 = 0, a2 = 0, a3 = 0;
#pragma unroll 4
    for (int d = 0; d < DIMF; d++) {
        float w = __ldg(W + d * DIMF + lt);
        unsigned long long w2 = pack2(w, w);
        const ulonglong2* xr = reinterpret_cast<const ulonglong2*>(xst + d * GNPB);
        ulonglong2 p0 = xr[0];
        ulonglong2 p1 = xr[1];
        a0 = fma2(p0.x, w2, a0);
        a1 = fma2(p0.y, w2, a1);
        a2 = fma2(p1.x, w2, a2);
        a3 = fma2(p1.y, w2, a3);
    }
    float v[GNPB];
    unpack2(a0, v[0], v[1]);
    unpack2(a1, v[2], v[3]);
    unpack2(a2, v[4], v[5]);
    unpack2(a3, v[6], v[7]);

    float* hb = d_h + (size_t)g * NN * DIMF;
#pragma unroll
    for (int u = 0; u < GNPB; u++) {
        int n = nb + u;
        if (n < NN) hb[(size_t)n * DIMF + lt] = v[u];
    }

    float as = __ldg(a_s + lt) * LOG2E;
    float ad = __ldg(a_d + lt) * LOG2E;
    float* asrc = d_asrc + (size_t)g * NN * NH;
    float* adst = d_adst + (size_t)g * NN * NH;
    int head = lt >> 4;
#pragma unroll
    for (int u = 0; u < GNPB; u++) {
        float vs = v[u] * as;
        float vd = v[u] * ad;
#pragma unroll
        for (int o = 8; o > 0; o >>= 1) {
            vs += __shfl_down_sync(0xffffffffu, vs, o, 16);
            vd += __shfl_down_sync(0xffffffffu, vd, o, 16);
        }
        if ((lt & 15) == 0) {
            int n = nb + u;
            if (n < NN) {
                asrc[(size_t)n * NH + head] = vs;
                adst[(size_t)n * NH + head] = vd;
            }
        }
    }
}

// ================== combined launch kernels ===================================

__global__ void __launch_bounds__(1024) k_phaseB(const float* __restrict__ ent0,
                                                 const float* __restrict__ W0,
                                                 const float* __restrict__ a_s,
                                                 const float* __restrict__ a_d,
                                                 const int* __restrict__ e0,
                                                 const int* __restrict__ e1) {
    __shared__ __align__(16) float smem[GGRP * DIMF * GNPB];
    int b = blockIdx.x;
    if (b < GB) dev_gemm_block(smem, b, 0, ent0, W0, a_s, a_d);
    else        dev_hist(b - GB, e0, e1);
}

__global__ void __launch_bounds__(1024) k_phaseC(const float* __restrict__ ent1,
                                                 const float* __restrict__ W0,
                                                 const float* __restrict__ a_s,
                                                 const float* __restrict__ a_d) {
    __shared__ __align__(16) float smem[GGRP * DIMF * GNPB];
    int b = blockIdx.x;
    if (b < 2) dev_scan(reinterpret_cast<int*>(smem), b);
    else       dev_gemm_block(smem, b - 2, 1, ent1, W0, a_s, a_d);
}

__global__ void __launch_bounds__(1024) k_scatnorm(const int* __restrict__ e0,
                                                   const int* __restrict__ e1,
                                                   const float* __restrict__ rel0,
                                                   const float* __restrict__ rel1) {
    int b = blockIdx.x;
    if (b < HB) dev_scatter(b, e0, e1);
    else        dev_normrel(b - HB, rel0, rel1);
}

__global__ void __launch_bounds__(1024) k_gemm_l1(const float* __restrict__ W1,
                                                  const float* __restrict__ a_s,
                                                  const float* __restrict__ a_d) {
    __shared__ __align__(16) float smem[GGRP * DIMF * GNPB];
    int b = blockIdx.x;
    int g = b >= GB;
    dev_gemm_block(smem, b - g * GB, g, d_x + (size_t)g * NN * DIMF, W1,
                   a_s, a_d);
}

// ---- agg: warp per dst node, 4-edge unroll + SOFTWARE PIPELINE -----------------
// Next iteration's csrc indices AND alpha loads are prefetched during the
// current iteration -> per-iteration unmet dependency is only the h-row loads
// (one L2 level, ~240cyc) instead of the 2-level csrc->alpha/h chain (~490cyc).
// LAST=0: ELU -> d_x.  LAST=1: feat + bf16 gnorm.
template <int LAST>
__device__ __forceinline__ void agg_body() {
    int gt = blockIdx.x * blockDim.x + threadIdx.x;
    int n = gt >> 5, lane = gt & 31;
    if (n >= NN) return;
    int g = blockIdx.y;
    const int* off = d_off + g * (NN + 1);
    const int* csrc = d_csrc + (size_t)g * EE;
    const float* hlane = d_h + (size_t)g * NN * DIMF + (lane << 2);
    const float* asb = d_asrc + (size_t)g * NN * NH;
    int head = lane >> 2;
    float adst_l = d_adst[(size_t)g * NN * NH + n * NH + head];

    int beg = off[n], end = off[n + 1];
    float4 acc = make_float4(0.f, 0.f, 0.f, 0.f);
    float den = 0.0f;

    int j = beg;
    if (j + 4 <= end) {
        // preload first group (indices + alphas)
        int s0 = __ldg(csrc + j);
        int s1 = __ldg(csrc + j + 1);
        int s2 = __ldg(csrc + j + 2);
        int s3 = __ldg(csrc + j + 3);
        float al0 = __ldg(asb + s0 * NH + head);
        float al1 = __ldg(asb + s1 * NH + head);
        float al2 = __ldg(asb + s2 * NH + head);
        float al3 = __ldg(asb + s3 * NH + head);
        while (true) {
            int jn = j + 4;
            bool more = (jn + 4 <= end);
            int p = more ? jn : j;          // safe re-read when last group
            // prefetch next indices
            int t0 = __ldg(csrc + p);
            int t1 = __ldg(csrc + p + 1);
            int t2 = __ldg(csrc + p + 2);
            int t3 = __ldg(csrc + p + 3);
            // current h loads (s known from previous iteration)
            float4 h0 = *reinterpret_cast<const float4*>(hlane + (size_t)s0 * DIMF);
            float4 h1 = *reinterpret_cast<const float4*>(hlane + (size_t)s1 * DIMF);
            float4 h2 = *reinterpret_cast<const float4*>(hlane + (size_t)s2 * DIMF);
            float4 h3 = *reinterpret_cast<const float4*>(hlane + (size_t)s3 * DIMF);
            // prefetch next alphas (depends on t; consumed next iteration)
            float b0 = __ldg(asb + t0 * NH + head);
            float b1 = __ldg(asb + t1 * NH + head);
            float b2 = __ldg(asb + t2 * NH + head);
            float b3 = __ldg(asb + t3 * NH + head);
            // weights from preloaded alphas
            float v0 = al0 + adst_l; v0 = fmaxf(v0, 0.2f * v0);
            float v1 = al1 + adst_l; v1 = fmaxf(v1, 0.2f * v1);
            float v2 = al2 + adst_l; v2 = fmaxf(v2, 0.2f * v2);
            float v3 = al3 + adst_l; v3 = fmaxf(v3, 0.2f * v3);
            float w0 = ex2(v0);
            float w1 = ex2(v1);
            float w2 = ex2(v2);
            float w3 = ex2(v3);
            den += (w0 + w1) + (w2 + w3);
            acc.x = fmaf(w0, h0.x, acc.x);
            acc.y = fmaf(w0, h0.y, acc.y);
            acc.z = fmaf(w0, h0.z, acc.z);
            acc.w = fmaf(w0, h0.w, acc.w);
            acc.x = fmaf(w1, h1.x, acc.x);
            acc.y = fmaf(w1, h1.y, acc.y);
            acc.z = fmaf(w1, h1.z, acc.z);
            acc.w = fmaf(w1, h1.w, acc.w);
            acc.x = fmaf(w2, h2.x, acc.x);
            acc.y = fmaf(w2, h2.y, acc.y);
            acc.z = fmaf(w2, h2.z, acc.z);
            acc.w = fmaf(w2, h2.w, acc.w);
            acc.x = fmaf(w3, h3.x, acc.x);
            acc.y = fmaf(w3, h3.y, acc.y);
            acc.z = fmaf(w3, h3.z, acc.z);
            acc.w = fmaf(w3, h3.w, acc.w);
            j = jn;
            if (!more) break;
            s0 = t0; s1 = t1; s2 = t2; s3 = t3;
            al0 = b0; al1 = b1; al2 = b2; al3 = b3;
        }
    }
    for (; j < end; j++) {
        int s0 = __ldg(csrc + j);
        float al0 = __ldg(asb + s0 * NH + head);
        float4 h0 = *reinterpret_cast<const float4*>(hlane + (size_t)s0 * DIMF);
        float v0 = al0 + adst_l; v0 = fmaxf(v0, 0.2f * v0);
        float w0 = ex2(v0);
        den += w0;
        acc.x = fmaf(w0, h0.x, acc.x);
        acc.y = fmaf(w0, h0.y, acc.y);
        acc.z = fmaf(w0, h0.z, acc.z);
        acc.w = fmaf(w0, h0.w, acc.w);
    }

    float inv = 1.0f / fmaxf(den, 1e-16f);
    acc.x *= inv; acc.y *= inv; acc.z *= inv; acc.w *= inv;

    if (LAST) {
        reinterpret_cast<float4*>(d_feat + (size_t)g * NN * DIMF +
                                  (size_t)n * DIMF)[lane] = acc;
        float s2 = acc.x * acc.x + acc.y * acc.y + acc.z * acc.z + acc.w * acc.w;
#pragma unroll
        for (int o = 16; o > 0; o >>= 1) s2 += __shfl_xor_sync(0xffffffffu, s2, o);
        float sc = 1.0f / fmaxf(sqrtf(s2), 1e-12f);
        uint2 bv = pack_bf16x4(acc.x * sc, acc.y * sc, acc.z * sc, acc.w * sc);
        reinterpret_cast<uint2*>(d_gnorm + (size_t)g * NN * DIMF +
                                 (size_t)n * DIMF)[lane] = bv;
    } else {
        acc.x = (acc.x > 0.f) ? acc.x : (__expf(acc.x) - 1.0f);
        acc.y = (acc.y > 0.f) ? acc.y : (__expf(acc.y) - 1.0f);
        acc.z = (acc.z > 0.f) ? acc.z : (__expf(acc.z) - 1.0f);
        acc.w = (acc.w > 0.f) ? acc.w : (__expf(acc.w) - 1.0f);
        reinterpret_cast<float4*>(d_x + (size_t)g * NN * DIMF +
                                  (size_t)n * DIMF)[lane] = acc;
    }
}

__global__ void __launch_bounds__(256, 4) k_agg0() { agg_body<0>(); }
__global__ void __launch_bounds__(256, 4) k_agg1() { agg_body<1>(); }

// ---- transE / rule-rs / gather merged ------------------------------------------
__device__ __forceinline__ float ad2(unsigned int a, unsigned int b, unsigned int c) {
    float2 fa = __bfloat1622float2(*reinterpret_cast<__nv_bfloat162*>(&a));
    float2 fb = __bfloat1622float2(*reinterpret_cast<__nv_bfloat162*>(&b));
    float2 fc = __bfloat1622float2(*reinterpret_cast<__nv_bfloat162*>(&c));
    return fabsf(fa.x + fb.x - fc.x) + fabsf(fa.y + fb.y - fc.y);
}
__device__ __forceinline__ float ad8(uint4 a, uint4 b, uint4 c) {
    return ad2(a.x, b.x, c.x) + ad2(a.y, b.y, c.y) +
           ad2(a.z, b.z, c.z) + ad2(a.w, b.w, c.w);
}
__device__ __forceinline__ float tv8(const __nv_bfloat16* gn,
                                     const __nv_bfloat16* rn,
                                     int hh, int tt, int rr, int lq) {
    const uint4* pa = reinterpret_cast<const uint4*>(gn + (size_t)hh * DIMF);
    const uint4* pb = reinterpret_cast<const uint4*>(rn + (size_t)rr * DIMF);
    const uint4* pc = reinterpret_cast<const uint4*>(gn + (size_t)tt * DIMF);
    uint4 a0 = pa[2 * lq], a1 = pa[2 * lq + 1];
    uint4 b0 = pb[2 * lq], b1 = pb[2 * lq + 1];
    uint4 c0 = pc[2 * lq], c1 = pc[2 * lq + 1];
    float s = ad8(a0, b0, c0) + ad8(a1, b1, c1);
    s += __shfl_xor_sync(0xffffffffu, s, 1);
    s += __shfl_xor_sync(0xffffffffu, s, 2);
    s += __shfl_xor_sync(0xffffffffu, s, 4);
    return 1.0f - s * TV_INV;
}

__global__ void __launch_bounds__(256) k_heads(
        const int* __restrict__ h0, const int* __restrict__ h1,
        const int* __restrict__ t0, const int* __restrict__ t1,
        const int* __restrict__ r0, const int* __restrict__ r1,
        const int* __restrict__ rh0, const int* __restrict__ rh1,
        const int* __restrict__ rt0, const int* __restrict__ rt1,
        const int* __restrict__ rr0, const int* __restrict__ rr1,
        float* __restrict__ outTv,
        const int* __restrict__ i0, const int* __restrict__ i1,
        float* __restrict__ outFeat) {
    int b = blockIdx.x;
    int g = blockIdx.y;
    const __nv_bfloat16* gn = d_gnorm + (size_t)g * NN * DIMF;
    const __nv_bfloat16* rn = d_rnorm + (size_t)g * NRELC * DIMF;
    if (b < TRB) {
        int gt = b * 256 + threadIdx.x;
        int warp = gt >> 5, lane = gt & 31;
        int sub = lane >> 3, lq = lane & 7;
        int w4 = warp * 4 + sub;
        if (w4 >= 2 * TT) return;
        const int* hI = g ? h1 : h0;
        const int* tI = g ? t1 : t0;
        const int* rI = g ? r1 : r0;
        float tv = tv8(gn, rn, hI[w4], tI[w4], rI[w4], lq);
        if (lq == 0) outTv[(size_t)g * 2 * TT + w4] = tv;
    } else if (b < TRB + RULEB) {
        int gt = (b - TRB) * 256 + threadIdx.x;
        int warp = gt >> 5, lane = gt & 31;
        if (warp * 4 >= RRULE) return;
        int sub = lane >> 3, lq = lane & 7;
        int w4 = warp * 4 + sub;
        const int* rh = g ? rh1 : rh0;
        const int* rt = g ? rt1 : rt0;
        const int* rr = g ? rr1 : rr0;
        float rs = tv8(gn, rn, rh[w4], rt[w4], rr[w4], lq);
        if (lq == 0) d_rs[(size_t)g * RRULE + w4] = rs;
    } else {
        int i = (b - TRB - RULEB) * 256 + threadIdx.x;
        if (i >= BB * DIMF) return;
        const int* idx = g ? i1 : i0;
        int bb = i >> 7, c = i & 127;
        outFeat[(size_t)g * BB * DIMF + i] =
            d_feat[(size_t)g * NN * DIMF + (size_t)idx[bb] * DIMF + c];
    }
}

__global__ void __launch_bounds__(256) k_rulefin(
        const int* __restrict__ pm0, const int* __restrict__ pm1,
        const float* __restrict__ tvbase, float* __restrict__ outRule) {
    int b = blockIdx.x;
    int g = blockIdx.y;
    if (b < RFB) {
        int i = b * 256 + threadIdx.x;
        if (i >= RRULE) return;
        const int* prem = g ? pm1 : pm0;
        const float* tv = tvbase + (size_t)g * 2 * TT;
        float rs = d_rs[(size_t)g * RRULE + i];
        int p0 = prem[i * 2 + 0];
        int p1 = prem[i * 2 + 1];
        float f1 = (p0 < TT) ? tv[p0 * 2 + g] : 1.0f;
        float f2 = (p1 < TT) ? tv[p1 * 2 + g] : 1.0f;
        outRule[(size_t)g * RRULE + i] = 1.0f + f1 * f2 * (rs - 1.0f);
    } else {
        int i = (b - RFB) * 256 + threadIdx.x;
        if (i < 2 * NN) d_cnt[i] = 0;
    }
}

// ---------------- host orchestration ------------------------------------------
static inline int nblk(long n, int t) { return (int)((n + t - 1) / t); }

extern "C" void kernel_launch(void* const* d_in, const int* in_sizes, int n_in,
                              void* d_out, int out_size) {
    const float* ent0 = (const float*)d_in[0];
    const float* ent1 = (const float*)d_in[1];
    const float* rel0 = (const float*)d_in[2];
    const float* rel1 = (const float*)d_in[3];
    const float* W    = (const float*)d_in[4];
    const float* a_s  = (const float*)d_in[5];
    const float* a_d  = (const float*)d_in[6];
    const int* dat0 = (const int*)d_in[7];
    const int* dat1 = (const int*)d_in[8];
    const int* edg0 = (const int*)d_in[9];
    const int* edg1 = (const int*)d_in[10];
    const int* h0 = (const int*)d_in[11];
    const int* t0 = (const int*)d_in[12];
    const int* r0 = (const int*)d_in[13];
    const int* h1 = (const int*)d_in[14];
    const int* t1 = (const int*)d_in[15];
    const int* r1 = (const int*)d_in[16];
    const int* rh0 = (const int*)d_in[17];
    const int* rt0 = (const int*)d_in[18];
    const int* rr0 = (const int*)d_in[19];
    const int* pm0 = (const int*)d_in[20];
    const int* rh1 = (const int*)d_in[21];
    const int* rt1 = (const int*)d_in[22];
    const int* rr1 = (const int*)d_in[23];
    const int* pm1 = (const int*)d_in[24];

    float* out      = (float*)d_out;
    float* out_feat = out;
    float* out_tv   = out + 2 * (size_t)BB * DIMF;
    float* out_rule = out_tv + 4 * (size_t)TT;

    const float* W0 = W;
    const float* W1 = W + (size_t)DIMF * DIMF;

    // 0: gemm+alpha(g0, l0) || hist
    k_phaseB<<<GB + HB, 1024>>>(ent0, W0, a_s, a_d, edg0, edg1);
    // 1: scan || gemm+alpha(g1, l0)
    k_phaseC<<<2 + GB, 1024>>>(ent1, W0, a_s, a_d);
    // 2: scatter || normrel
    k_scatnorm<<<HB + RB, 1024>>>(edg0, edg1, rel0, rel1);
    // 3: layer-0 aggregate  <-- the launch ncu profiles
    k_agg0<<<dim3(nblk((long)NN * 32, 256), 2), 256>>>();
    // 4: layer-1 gemm+alpha
    k_gemm_l1<<<2 * GB, 1024>>>(W1, a_s + DIMF, a_d + DIMF);
    // 5: layer-1 aggregate (feat + bf16 gnorm)
    k_agg1<<<dim3(nblk((long)NN * 32, 256), 2), 256>>>();
    // 6: transe || rule-rs || gather
    k_heads<<<dim3(TRB + RULEB + GATB, 2), 256>>>(h0, h1, t0, t1, r0, r1,
                                                  rh0, rh1, rt0, rt1, rr0, rr1,
                                                  out_tv, dat0, dat1, out_feat);
    // 7: rule combine || tail-zero
    k_rulefin<<<dim3(RFB + ZTB, 2), 256>>>(pm0, pm1, out_tv, out_rule);

    (void)in_sizes; (void)n_in; (void)out_size;
}

// round 17
// speedup vs baseline: 1.0999x; 1.0524x over previous
#include <cuda_runtime.h>
#include <cuda_bf16.h>
#include <cuda_fp16.h>
#include <math.h>

#define NN    50000
#define DIMF  128
#define NH    8
#define EE    800000
#define NRELC 2000
#define TT    200000
#define RRULE 50000
#define BB    10000
#define TV_INV 0.029462782549439483f   // 1/(3*sqrt(128))
#define LOG2E 1.4426950408889634f

#define GNPB   8
#define GGRP   8
#define GNODES (GNPB * GGRP)
#define GB     ((NN + GNODES - 1) / GNODES)       // 782 gemm blocks per graph
#define RB     ((2 * NRELC + 31) / 32)            // 125 normrel blocks
#define HB     ((2 * EE + 1023) / 1024)           // 1563 hist/scatter blocks
#define TRB    12500                              // transe blocks (256 thr)
#define RULEB  (((RRULE / 4) + 7) / 8)            // 1563 rule-rs blocks
#define GATB   ((BB * DIMF + 255) / 256)          // 5000 gather blocks
#define RFB    ((RRULE + 255) / 256)              // 196 rule-combine blocks
#define ZTB    ((2 * NN + 255) / 256)             // 391 tail-zero blocks

// ---------------- device scratch (zero-initialized at module load) -------------
__device__ __align__(16) float d_x[2 * NN * DIMF];
__device__ __align__(16) __half d_h16[2 * NN * DIMF];  // layer-0 h (fp16)
__device__ __align__(16) float  d_h[2 * NN * DIMF];    // layer-1 h (fp32)
__device__ float               d_asrc[2 * NN * NH];  // prescaled by log2(e)
__device__ float               d_adst[2 * NN * NH];  // prescaled by log2(e)
__device__ __align__(16) float d_feat[2 * NN * DIMF];
__device__ __align__(16) __nv_bfloat16 d_gnorm[2 * NN * DIMF];
__device__ __align__(16) __nv_bfloat16 d_rnorm[2 * NRELC * DIMF];
__device__ float d_rs[2 * RRULE];
__device__ int d_cnt[2 * NN];
__device__ int d_off[2 * (NN + 1)];
__device__ int d_cur[2 * NN];
__device__ __align__(16) int d_csrc[2 * EE];

// ---------------- packed helpers ----------------------------------------------
__device__ __forceinline__ unsigned long long pack2(float x, float y) {
    unsigned long long r;
    asm("mov.b64 %0, {%1, %2};" : "=l"(r) : "f"(x), "f"(y));
    return r;
}
__device__ __forceinline__ void unpack2(unsigned long long v, float& x, float& y) {
    asm("mov.b64 {%0, %1}, %2;" : "=f"(x), "=f"(y) : "l"(v));
}
__device__ __forceinline__ unsigned long long fma2(unsigned long long a,
                                                   unsigned long long b,
                                                   unsigned long long c) {
    unsigned long long r;
    asm("fma.rn.f32x2 %0, %1, %2, %3;" : "=l"(r) : "l"(a), "l"(b), "l"(c));
    return r;
}
__device__ __forceinline__ float ex2(float x) {
    float r;
    asm("ex2.approx.f32 %0, %1;" : "=f"(r) : "f"(x));
    return r;
}
__device__ __forceinline__ uint2 pack_bf16x4(float a, float b, float c, float d) {
    __nv_bfloat162 p0 = __floats2bfloat162_rn(a, b);
    __nv_bfloat162 p1 = __floats2bfloat162_rn(c, d);
    uint2 u;
    u.x = *reinterpret_cast<unsigned int*>(&p0);
    u.y = *reinterpret_cast<unsigned int*>(&p1);
    return u;
}

// ================== device building blocks =====================================

__device__ __forceinline__ void dev_normrel(int b, const float* __restrict__ rel0,
                                            const float* __restrict__ rel1) {
    int wid = threadIdx.x >> 5, lane = threadIdx.x & 31;
    int row = b * 32 + wid;
    if (row >= 2 * NRELC) return;
    int g = row >= NRELC;
    int r = row - g * NRELC;
    const float* rel = g ? rel1 : rel0;
    float4 v = reinterpret_cast<const float4*>(rel + (size_t)r * DIMF)[lane];
    float s = v.x * v.x + v.y * v.y + v.z * v.z + v.w * v.w;
#pragma unroll
    for (int o = 16; o > 0; o >>= 1) s += __shfl_xor_sync(0xffffffffu, s, o);
    float sc = 1.0f / fmaxf(sqrtf(s), 1e-12f);
    uint2 bv = pack_bf16x4(v.x * sc, v.y * sc, v.z * sc, v.w * sc);
    reinterpret_cast<uint2*>(d_rnorm + (size_t)g * NRELC * DIMF +
                             (size_t)r * DIMF)[lane] = bv;
}

__device__ __forceinline__ void dev_hist(int b, const int* __restrict__ e0,
                                         const int* __restrict__ e1) {
    int idx = b * 1024 + threadIdx.x;
    if (idx >= 2 * EE) return;
    int g = idx >= EE;
    int e = idx - g * EE;
    const int* edg = g ? e1 : e0;
    atomicAdd(&d_cnt[g * NN + edg[EE + e]], 1);
}

__device__ __forceinline__ void dev_scatter(int b, const int* __restrict__ e0,
                                            const int* __restrict__ e1) {
    int idx = b * 1024 + threadIdx.x;
    if (idx >= 2 * EE) return;
    int g = idx >= EE;
    int e = idx - g * EE;
    const int* edg = g ? e1 : e0;
    int s = edg[e];
    int d = edg[EE + e];
    int p = atomicAdd(&d_cur[g * NN + d], 1);
    d_csrc[(size_t)g * EE + p] = s;
}

__device__ __forceinline__ void dev_scan(int* wsum, int g) {
    int t = threadIdx.x;
    int lane = t & 31, wid = t >> 5;
    const int NCH = (NN + 1023) / 1024;
    int run = 0;
    int val = (t < NN) ? d_cnt[g * NN + t] : 0;
    for (int c = 0; c < NCH; c++) {
        int inext = (c + 1) * 1024 + t;
        int vnext = (c + 1 < NCH && inext < NN) ? d_cnt[g * NN + inext] : 0;
        int incl = val;
#pragma unroll
        for (int o = 1; o < 32; o <<= 1) {
            int u = __shfl_up_sync(0xffffffffu, incl, o);
            if (lane >= o) incl += u;
        }
        if (lane == 31) wsum[wid] = incl;
        __syncthreads();
        if (wid == 0) {
            int ws = wsum[lane];
#pragma unroll
            for (int o = 1; o < 32; o <<= 1) {
                int u = __shfl_up_sync(0xffffffffu, ws, o);
                if (lane >= o) ws += u;
            }
            wsum[lane] = ws;
        }
        __syncthreads();
        int wb = (wid > 0) ? wsum[wid - 1] : 0;
        int i = c * 1024 + t;
        int excl = run + wb + incl - val;
        if (i < NN) {
            d_off[g * (NN + 1) + i] = excl;
            d_cur[g * NN + i] = excl;
        }
        run += wsum[31];
        __syncthreads();
        val = vnext;
    }
    if (t == 0) d_off[g * (NN + 1) + NN] = EE;
}

// gemm block with FUSED alpha epilogue; alphas prescaled by log2(e).
// L0=1: store fp16 h to d_h16.  L0=0: store fp32 h to d_h.
template <int L0>
__device__ __forceinline__ void dev_gemm_block(float* smem, int nodeblk, int g,
                                               const float* __restrict__ xsrc,
                                               const float* __restrict__ W,
                                               const float* __restrict__ a_s,
                                               const float* __restrict__ a_d) {
    int t = threadIdx.x;
    int grp = t >> 7, lt = t & 127;
    float* xst = smem + grp * (DIMF * GNPB);
    int nb = nodeblk * GNODES + grp * GNPB;

    for (int k = lt; k < GNPB * DIMF; k += 128) {
        int u = k >> 7, d = k & 127;
        int n = nb + u;
        xst[d * GNPB + u] = (n < NN) ? xsrc[(size_t)n * DIMF + d] : 0.0f;
    }
    __syncthreads();

    unsigned long long a0 = 0, a1 = 0, a2 = 0, a3 = 0;
#pragma unroll 4
    for (int d = 0; d < DIMF; d++) {
        float w = __ldg(W + d * DIMF + lt);
        unsigned long long w2 = pack2(w, w);
        const ulonglong2* xr = reinterpret_cast<const ulonglong2*>(xst + d * GNPB);
        ulonglong2 p0 = xr[0];
        ulonglong2 p1 = xr[1];
        a0 = fma2(p0.x, w2, a0);
        a1 = fma2(p0.y, w2, a1);
        a2 = fma2(p1.x, w2, a2);
        a3 = fma2(p1.y, w2, a3);
    }
    float v[GNPB];
    unpack2(a0, v[0], v[1]);
    unpack2(a1, v[2], v[3]);
    unpack2(a2, v[4], v[5]);
    unpack2(a3, v[6], v[7]);

    if (L0) {
        __half* hb = d_h16 + (size_t)g * NN * DIMF;
#pragma unroll
        for (int u = 0; u < GNPB; u++) {
            int n = nb + u;
            if (n < NN) hb[(size_t)n * DIMF + lt] = __float2half_rn(v[u]);
        }
    } else {
        float* hb = d_h + (size_t)g * NN * DIMF;
#pragma unroll
        for (int u = 0; u < GNPB; u++) {
            int n = nb + u;
            if (n < NN) hb[(size_t)n * DIMF + lt] = v[u];
        }
    }

    float as = __ldg(a_s + lt) * LOG2E;
    float ad = __ldg(a_d + lt) * LOG2E;
    float* asrc = d_asrc + (size_t)g * NN * NH;
    float* adst = d_adst + (size_t)g * NN * NH;
    int head = lt >> 4;
#pragma unroll
    for (int u = 0; u < GNPB; u++) {
        float vs = v[u] * as;
        float vd = v[u] * ad;
#pragma unroll
        for (int o = 8; o > 0; o >>= 1) {
            vs += __shfl_down_sync(0xffffffffu, vs, o, 16);
            vd += __shfl_down_sync(0xffffffffu, vd, o, 16);
        }
        if ((lt & 15) == 0) {
            int n = nb + u;
            if (n < NN) {
                asrc[(size_t)n * NH + head] = vs;
                adst[(size_t)n * NH + head] = vd;
            }
        }
    }
}

// ================== combined launch kernels ===================================

__global__ void __launch_bounds__(1024) k_phaseB(const float* __restrict__ ent0,
                                                 const float* __restrict__ W0,
                                                 const float* __restrict__ a_s,
                                                 const float* __restrict__ a_d,
                                                 const int* __restrict__ e0,
                                                 const int* __restrict__ e1) {
    __shared__ __align__(16) float smem[GGRP * DIMF * GNPB];
    int b = blockIdx.x;
    if (b < GB) dev_gemm_block<1>(smem, b, 0, ent0, W0, a_s, a_d);
    else        dev_hist(b - GB, e0, e1);
}

__global__ void __launch_bounds__(1024) k_phaseC(const float* __restrict__ ent1,
                                                 const float* __restrict__ W0,
                                                 const float* __restrict__ a_s,
                                                 const float* __restrict__ a_d) {
    __shared__ __align__(16) float smem[GGRP * DIMF * GNPB];
    int b = blockIdx.x;
    if (b < 2) dev_scan(reinterpret_cast<int*>(smem), b);
    else       dev_gemm_block<1>(smem, b - 2, 1, ent1, W0, a_s, a_d);
}

__global__ void __launch_bounds__(1024) k_scatnorm(const int* __restrict__ e0,
                                                   const int* __restrict__ e1,
                                                   const float* __restrict__ rel0,
                                                   const float* __restrict__ rel1) {
    int b = blockIdx.x;
    if (b < HB) dev_scatter(b, e0, e1);
    else        dev_normrel(b - HB, rel0, rel1);
}

__global__ void __launch_bounds__(1024) k_gemm_l1(const float* __restrict__ W1,
                                                  const float* __restrict__ a_s,
                                                  const float* __restrict__ a_d) {
    __shared__ __align__(16) float smem[GGRP * DIMF * GNPB];
    int b = blockIdx.x;
    int g = b >= GB;
    dev_gemm_block<0>(smem, b - g * GB, g, d_x + (size_t)g * NN * DIMF, W1,
                      a_s, a_d);
}

// ---- agg0: R13 body over fp16 h rows (256B/row -> half the gather traffic) ----
__global__ void __launch_bounds__(256, 5) k_agg0() {
    int gt = blockIdx.x * blockDim.x + threadIdx.x;
    int n = gt >> 5, lane = gt & 31;
    if (n >= NN) return;
    int g = blockIdx.y;
    const int* off = d_off + g * (NN + 1);
    const int* csrc = d_csrc + (size_t)g * EE;
    const __half* hlane = d_h16 + (size_t)g * NN * DIMF + (lane << 2);
    const float* asb = d_asrc + (size_t)g * NN * NH;
    int head = lane >> 2;
    float adst_l = d_adst[(size_t)g * NN * NH + n * NH + head];

    int beg = off[n], end = off[n + 1];
    float4 acc = make_float4(0.f, 0.f, 0.f, 0.f);
    float den = 0.0f;

    int j = beg;
    for (; j + 4 <= end; j += 4) {
        int s0 = __ldg(csrc + j);
        int s1 = __ldg(csrc + j + 1);
        int s2 = __ldg(csrc + j + 2);
        int s3 = __ldg(csrc + j + 3);
        float al0 = __ldg(asb + s0 * NH + head);
        float al1 = __ldg(asb + s1 * NH + head);
        float al2 = __ldg(asb + s2 * NH + head);
        float al3 = __ldg(asb + s3 * NH + head);
        uint2 u0 = *reinterpret_cast<const uint2*>(hlane + (size_t)s0 * DIMF);
        uint2 u1 = *reinterpret_cast<const uint2*>(hlane + (size_t)s1 * DIMF);
        uint2 u2 = *reinterpret_cast<const uint2*>(hlane + (size_t)s2 * DIMF);
        uint2 u3 = *reinterpret_cast<const uint2*>(hlane + (size_t)s3 * DIMF);
        float v0 = al0 + adst_l; v0 = fmaxf(v0, 0.2f * v0);
        float v1 = al1 + adst_l; v1 = fmaxf(v1, 0.2f * v1);
        float v2 = al2 + adst_l; v2 = fmaxf(v2, 0.2f * v2);
        float v3 = al3 + adst_l; v3 = fmaxf(v3, 0.2f * v3);
        float w0 = ex2(v0);
        float w1 = ex2(v1);
        float w2 = ex2(v2);
        float w3 = ex2(v3);
        den += (w0 + w1) + (w2 + w3);
        float2 a0 = __half22float2(*reinterpret_cast<__half2*>(&u0.x));
        float2 b0 = __half22float2(*reinterpret_cast<__half2*>(&u0.y));
        float2 a1 = __half22float2(*reinterpret_cast<__half2*>(&u1.x));
        float2 b1 = __half22float2(*reinterpret_cast<__half2*>(&u1.y));
        float2 a2 = __half22float2(*reinterpret_cast<__half2*>(&u2.x));
        float2 b2 = __half22float2(*reinterpret_cast<__half2*>(&u2.y));
        float2 a3 = __half22float2(*reinterpret_cast<__half2*>(&u3.x));
        float2 b3 = __half22float2(*reinterpret_cast<__half2*>(&u3.y));
        acc.x = fmaf(w0, a0.x, acc.x);
        acc.y = fmaf(w0, a0.y, acc.y);
        acc.z = fmaf(w0, b0.x, acc.z);
        acc.w = fmaf(w0, b0.y, acc.w);
        acc.x = fmaf(w1, a1.x, acc.x);
        acc.y = fmaf(w1, a1.y, acc.y);
        acc.z = fmaf(w1, b1.x, acc.z);
        acc.w = fmaf(w1, b1.y, acc.w);
        acc.x = fmaf(w2, a2.x, acc.x);
        acc.y = fmaf(w2, a2.y, acc.y);
        acc.z = fmaf(w2, b2.x, acc.z);
        acc.w = fmaf(w2, b2.y, acc.w);
        acc.x = fmaf(w3, a3.x, acc.x);
        acc.y = fmaf(w3, a3.y, acc.y);
        acc.z = fmaf(w3, b3.x, acc.z);
        acc.w = fmaf(w3, b3.y, acc.w);
    }
    for (; j < end; j++) {
        int s0 = __ldg(csrc + j);
        float al0 = __ldg(asb + s0 * NH + head);
        uint2 u0 = *reinterpret_cast<const uint2*>(hlane + (size_t)s0 * DIMF);
        float v0 = al0 + adst_l; v0 = fmaxf(v0, 0.2f * v0);
        float w0 = ex2(v0);
        den += w0;
        float2 a0 = __half22float2(*reinterpret_cast<__half2*>(&u0.x));
        float2 b0 = __half22float2(*reinterpret_cast<__half2*>(&u0.y));
        acc.x = fmaf(w0, a0.x, acc.x);
        acc.y = fmaf(w0, a0.y, acc.y);
        acc.z = fmaf(w0, b0.x, acc.z);
        acc.w = fmaf(w0, b0.y, acc.w);
    }

    float inv = 1.0f / fmaxf(den, 1e-16f);
    acc.x *= inv; acc.y *= inv; acc.z *= inv; acc.w *= inv;

    acc.x = (acc.x > 0.f) ? acc.x : (__expf(acc.x) - 1.0f);
    acc.y = (acc.y > 0.f) ? acc.y : (__expf(acc.y) - 1.0f);
    acc.z = (acc.z > 0.f) ? acc.z : (__expf(acc.z) - 1.0f);
    acc.w = (acc.w > 0.f) ? acc.w : (__expf(acc.w) - 1.0f);
    reinterpret_cast<float4*>(d_x + (size_t)g * NN * DIMF +
                              (size_t)n * DIMF)[lane] = acc;
}

// ---- agg1: R13 body over fp32 h rows; writes feat + bf16 gnorm -----------------
__global__ void __launch_bounds__(256, 5) k_agg1() {
    int gt = blockIdx.x * blockDim.x + threadIdx.x;
    int n = gt >> 5, lane = gt & 31;
    if (n >= NN) return;
    int g = blockIdx.y;
    const int* off = d_off + g * (NN + 1);
    const int* csrc = d_csrc + (size_t)g * EE;
    const float* hlane = d_h + (size_t)g * NN * DIMF + (lane << 2);
    const float* asb = d_asrc + (size_t)g * NN * NH;
    int head = lane >> 2;
    float adst_l = d_adst[(size_t)g * NN * NH + n * NH + head];

    int beg = off[n], end = off[n + 1];
    float4 acc = make_float4(0.f, 0.f, 0.f, 0.f);
    float den = 0.0f;

    int j = beg;
    for (; j + 4 <= end; j += 4) {
        int s0 = __ldg(csrc + j);
        int s1 = __ldg(csrc + j + 1);
        int s2 = __ldg(csrc + j + 2);
        int s3 = __ldg(csrc + j + 3);
        float al0 = __ldg(asb + s0 * NH + head);
        float al1 = __ldg(asb + s1 * NH + head);
        float al2 = __ldg(asb + s2 * NH + head);
        float al3 = __ldg(asb + s3 * NH + head);
        float4 h0 = *reinterpret_cast<const float4*>(hlane + (size_t)s0 * DIMF);
        float4 h1 = *reinterpret_cast<const float4*>(hlane + (size_t)s1 * DIMF);
        float4 h2 = *reinterpret_cast<const float4*>(hlane + (size_t)s2 * DIMF);
        float4 h3 = *reinterpret_cast<const float4*>(hlane + (size_t)s3 * DIMF);
        float v0 = al0 + adst_l; v0 = fmaxf(v0, 0.2f * v0);
        float v1 = al1 + adst_l; v1 = fmaxf(v1, 0.2f * v1);
        float v2 = al2 + adst_l; v2 = fmaxf(v2, 0.2f * v2);
        float v3 = al3 + adst_l; v3 = fmaxf(v3, 0.2f * v3);
        float w0 = ex2(v0);
        float w1 = ex2(v1);
        float w2 = ex2(v2);
        float w3 = ex2(v3);
        den += (w0 + w1) + (w2 + w3);
        acc.x = fmaf(w0, h0.x, acc.x);
        acc.y = fmaf(w0, h0.y, acc.y);
        acc.z = fmaf(w0, h0.z, acc.z);
        acc.w = fmaf(w0, h0.w, acc.w);
        acc.x = fmaf(w1, h1.x, acc.x);
        acc.y = fmaf(w1, h1.y, acc.y);
        acc.z = fmaf(w1, h1.z, acc.z);
        acc.w = fmaf(w1, h1.w, acc.w);
        acc.x = fmaf(w2, h2.x, acc.x);
        acc.y = fmaf(w2, h2.y, acc.y);
        acc.z = fmaf(w2, h2.z, acc.z);
        acc.w = fmaf(w2, h2.w, acc.w);
        acc.x = fmaf(w3, h3.x, acc.x);
        acc.y = fmaf(w3, h3.y, acc.y);
        acc.z = fmaf(w3, h3.z, acc.z);
        acc.w = fmaf(w3, h3.w, acc.w);
    }
    for (; j < end; j++) {
        int s0 = __ldg(csrc + j);
        float al0 = __ldg(asb + s0 * NH + head);
        float4 h0 = *reinterpret_cast<const float4*>(hlane + (size_t)s0 * DIMF);
        float v0 = al0 + adst_l; v0 = fmaxf(v0, 0.2f * v0);
        float w0 = ex2(v0);
        den += w0;
        acc.x = fmaf(w0, h0.x, acc.x);
        acc.y = fmaf(w0, h0.y, acc.y);
        acc.z = fmaf(w0, h0.z, acc.z);
        acc.w = fmaf(w0, h0.w, acc.w);
    }

    float inv = 1.0f / fmaxf(den, 1e-16f);
    acc.x *= inv; acc.y *= inv; acc.z *= inv; acc.w *= inv;

    reinterpret_cast<float4*>(d_feat + (size_t)g * NN * DIMF +
                              (size_t)n * DIMF)[lane] = acc;
    float s2 = acc.x * acc.x + acc.y * acc.y + acc.z * acc.z + acc.w * acc.w;
#pragma unroll
    for (int o = 16; o > 0; o >>= 1) s2 += __shfl_xor_sync(0xffffffffu, s2, o);
    float sc = 1.0f / fmaxf(sqrtf(s2), 1e-12f);
    uint2 bv = pack_bf16x4(acc.x * sc, acc.y * sc, acc.z * sc, acc.w * sc);
    reinterpret_cast<uint2*>(d_gnorm + (size_t)g * NN * DIMF +
                             (size_t)n * DIMF)[lane] = bv;
}

// ---- transE / rule-rs / gather merged ------------------------------------------
__device__ __forceinline__ float ad2(unsigned int a, unsigned int b, unsigned int c) {
    float2 fa = __bfloat1622float2(*reinterpret_cast<__nv_bfloat162*>(&a));
    float2 fb = __bfloat1622float2(*reinterpret_cast<__nv_bfloat162*>(&b));
    float2 fc = __bfloat1622float2(*reinterpret_cast<__nv_bfloat162*>(&c));
    return fabsf(fa.x + fb.x - fc.x) + fabsf(fa.y + fb.y - fc.y);
}
__device__ __forceinline__ float ad8(uint4 a, uint4 b, uint4 c) {
    return ad2(a.x, b.x, c.x) + ad2(a.y, b.y, c.y) +
           ad2(a.z, b.z, c.z) + ad2(a.w, b.w, c.w);
}
__device__ __forceinline__ float tv8(const __nv_bfloat16* gn,
                                     const __nv_bfloat16* rn,
                                     int hh, int tt, int rr, int lq) {
    const uint4* pa = reinterpret_cast<const uint4*>(gn + (size_t)hh * DIMF);
    const uint4* pb = reinterpret_cast<const uint4*>(rn + (size_t)rr * DIMF);
    const uint4* pc = reinterpret_cast<const uint4*>(gn + (size_t)tt * DIMF);
    uint4 a0 = pa[2 * lq], a1 = pa[2 * lq + 1];
    uint4 b0 = pb[2 * lq], b1 = pb[2 * lq + 1];
    uint4 c0 = pc[2 * lq], c1 = pc[2 * lq + 1];
    float s = ad8(a0, b0, c0) + ad8(a1, b1, c1);
    s += __shfl_xor_sync(0xffffffffu, s, 1);
    s += __shfl_xor_sync(0xffffffffu, s, 2);
    s += __shfl_xor_sync(0xffffffffu, s, 4);
    return 1.0f - s * TV_INV;
}

__global__ void __launch_bounds__(256) k_heads(
        const int* __restrict__ h0, const int* __restrict__ h1,
        const int* __restrict__ t0, const int* __restrict__ t1,
        const int* __restrict__ r0, const int* __restrict__ r1,
        const int* __restrict__ rh0, const int* __restrict__ rh1,
        const int* __restrict__ rt0, const int* __restrict__ rt1,
        const int* __restrict__ rr0, const int* __restrict__ rr1,
        float* __restrict__ outTv,
        const int* __restrict__ i0, const int* __restrict__ i1,
        float* __restrict__ outFeat) {
    int b = blockIdx.x;
    int g = blockIdx.y;
    const __nv_bfloat16* gn = d_gnorm + (size_t)g * NN * DIMF;
    const __nv_bfloat16* rn = d_rnorm + (size_t)g * NRELC * DIMF;
    if (b < TRB) {
        int gt = b * 256 + threadIdx.x;
        int warp = gt >> 5, lane = gt & 31;
        int sub = lane >> 3, lq = lane & 7;
        int w4 = warp * 4 + sub;
        if (w4 >= 2 * TT) return;
        const int* hI = g ? h1 : h0;
        const int* tI = g ? t1 : t0;
        const int* rI = g ? r1 : r0;
        float tv = tv8(gn, rn, hI[w4], tI[w4], rI[w4], lq);
        if (lq == 0) outTv[(size_t)g * 2 * TT + w4] = tv;
    } else if (b < TRB + RULEB) {
        int gt = (b - TRB) * 256 + threadIdx.x;
        int warp = gt >> 5, lane = gt & 31;
        if (warp * 4 >= RRULE) return;
        int sub = lane >> 3, lq = lane & 7;
        int w4 = warp * 4 + sub;
        const int* rh = g ? rh1 : rh0;
        const int* rt = g ? rt1 : rt0;
        const int* rr = g ? rr1 : rr0;
        float rs = tv8(gn, rn, rh[w4], rt[w4], rr[w4], lq);
        if (lq == 0) d_rs[(size_t)g * RRULE + w4] = rs;
    } else {
        int i = (b - TRB - RULEB) * 256 + threadIdx.x;
        if (i >= BB * DIMF) return;
        const int* idx = g ? i1 : i0;
        int bb = i >> 7, c = i & 127;
        outFeat[(size_t)g * BB * DIMF + i] =
            d_feat[(size_t)g * NN * DIMF + (size_t)idx[bb] * DIMF + c];
    }
}

__global__ void __launch_bounds__(256) k_rulefin(
        const int* __restrict__ pm0, const int* __restrict__ pm1,
        const float* __restrict__ tvbase, float* __restrict__ outRule) {
    int b = blockIdx.x;
    int g = blockIdx.y;
    if (b < RFB) {
        int i = b * 256 + threadIdx.x;
        if (i >= RRULE) return;
        const int* prem = g ? pm1 : pm0;
        const float* tv = tvbase + (size_t)g * 2 * TT;
        float rs = d_rs[(size_t)g * RRULE + i];
        int p0 = prem[i * 2 + 0];
        int p1 = prem[i * 2 + 1];
        float f1 = (p0 < TT) ? tv[p0 * 2 + g] : 1.0f;
        float f2 = (p1 < TT) ? tv[p1 * 2 + g] : 1.0f;
        outRule[(size_t)g * RRULE + i] = 1.0f + f1 * f2 * (rs - 1.0f);
    } else {
        int i = (b - RFB) * 256 + threadIdx.x;
        if (i < 2 * NN) d_cnt[i] = 0;
    }
}

// ---------------- host orchestration ------------------------------------------
static inline int nblk(long n, int t) { return (int)((n + t - 1) / t); }

extern "C" void kernel_launch(void* const* d_in, const int* in_sizes, int n_in,
                              void* d_out, int out_size) {
    const float* ent0 = (const float*)d_in[0];
    const float* ent1 = (const float*)d_in[1];
    const float* rel0 = (const float*)d_in[2];
    const float* rel1 = (const float*)d_in[3];
    const float* W    = (const float*)d_in[4];
    const float* a_s  = (const float*)d_in[5];
    const float* a_d  = (const float*)d_in[6];
    const int* dat0 = (const int*)d_in[7];
    const int* dat1 = (const int*)d_in[8];
    const int* edg0 = (const int*)d_in[9];
    const int* edg1 = (const int*)d_in[10];
    const int* h0 = (const int*)d_in[11];
    const int* t0 = (const int*)d_in[12];
    const int* r0 = (const int*)d_in[13];
    const int* h1 = (const int*)d_in[14];
    const int* t1 = (const int*)d_in[15];
    const int* r1 = (const int*)d_in[16];
    const int* rh0 = (const int*)d_in[17];
    const int* rt0 = (const int*)d_in[18];
    const int* rr0 = (const int*)d_in[19];
    const int* pm0 = (const int*)d_in[20];
    const int* rh1 = (const int*)d_in[21];
    const int* rt1 = (const int*)d_in[22];
    const int* rr1 = (const int*)d_in[23];
    const int* pm1 = (const int*)d_in[24];

    float* out      = (float*)d_out;
    float* out_feat = out;
    float* out_tv   = out + 2 * (size_t)BB * DIMF;
    float* out_rule = out_tv + 4 * (size_t)TT;

    const float* W0 = W;
    const float* W1 = W + (size_t)DIMF * DIMF;

    // 0: gemm+alpha(g0, l0; fp16 h) || hist
    k_phaseB<<<GB + HB, 1024>>>(ent0, W0, a_s, a_d, edg0, edg1);
    // 1: scan || gemm+alpha(g1, l0; fp16 h)
    k_phaseC<<<2 + GB, 1024>>>(ent1, W0, a_s, a_d);
    // 2: scatter || normrel
    k_scatnorm<<<HB + RB, 1024>>>(edg0, edg1, rel0, rel1);
    // 3: layer-0 aggregate (fp16 h)  <-- the launch ncu profiles
    k_agg0<<<dim3(nblk((long)NN * 32, 256), 2), 256>>>();
    // 4: layer-1 gemm+alpha (fp32 h)
    k_gemm_l1<<<2 * GB, 1024>>>(W1, a_s + DIMF, a_d + DIMF);
    // 5: layer-1 aggregate (feat + bf16 gnorm)
    k_agg1<<<dim3(nblk((long)NN * 32, 256), 2), 256>>>();
    // 6: transe || rule-rs || gather
    k_heads<<<dim3(TRB + RULEB + GATB, 2), 256>>>(h0, h1, t0, t1, r0, r1,
                                                  rh0, rh1, rt0, rt1, rr0, rr1,
                                                  out_tv, dat0, dat1, out_feat);
    // 7: rule combine || tail-zero
    k_rulefin<<<dim3(RFB + ZTB, 2), 256>>>(pm0, pm1, out_tv, out_rule);

    (void)in_sizes; (void)n_in; (void)out_size;
}